// round 9
// baseline (speedup 1.0000x reference)
#include <cuda_runtime.h>
#include <cstdint>

#define BB 512
#define NN 90
#define DD 1024
#define KK 45
#define THREADS 1024
#define WARPS 32
#define CLUSTER 4
#define ROWS_PER_CTA 45                      // one (tensor, half) tile
#define BUF_BYTES (ROWS_PER_CTA * DD * 4)    // 184320 B dynamic smem

__device__ unsigned g_task_counter;
__device__ unsigned g_done;

__device__ __forceinline__ uint32_t smem_u32(const void* p) {
    uint32_t a;
    asm("{ .reg .u64 t; cvta.to.shared.u64 t, %1; cvt.u32.u64 %0, t; }"
        : "=r"(a) : "l"(p));
    return a;
}
__device__ __forceinline__ void dsmem_st_u32(uint32_t local_addr, uint32_t peer, unsigned v) {
    uint32_t r;
    asm volatile("mapa.shared::cluster.u32 %0, %1, %2;" : "=r"(r) : "r"(local_addr), "r"(peer));
    asm volatile("st.shared::cluster.u32 [%0], %1;" :: "r"(r), "r"(v) : "memory");
}
__device__ __forceinline__ void dsmem_st_f32(uint32_t local_addr, uint32_t peer, float v) {
    uint32_t r;
    asm volatile("mapa.shared::cluster.u32 %0, %1, %2;" : "=r"(r) : "r"(local_addr), "r"(peer));
    asm volatile("st.shared::cluster.f32 [%0], %1;" :: "r"(r), "f"(v) : "memory");
}
__device__ __forceinline__ void cluster_sync() {
    asm volatile("barrier.cluster.arrive.aligned;" ::: "memory");
    asm volatile("barrier.cluster.wait.aligned;" ::: "memory");
}

__global__ __launch_bounds__(THREADS, 1) __cluster_dims__(CLUSTER, 1, 1)
void multig_pool_kernel(const float* __restrict__ x_sc,
                        const float* __restrict__ x_fc,
                        const float* __restrict__ pool_w,
                        const float* __restrict__ multi_w,
                        const float* __restrict__ multi_b,
                        float* __restrict__ out)
{
    extern __shared__ __align__(16) float4 buf4[];   // 45 rows x 1024 f32
    __shared__ __align__(16) float spw[DD];
    __shared__ float s_alltanh[2 * NN];   // [tensor][node]
    __shared__ float s_part[NN * 2];      // per-(row,half) dot partials
    __shared__ float s_scores[NN];
    __shared__ int   sel_idx[KK];
    __shared__ float sel_w[KK];
    __shared__ float red[WARPS];
    __shared__ float s_invnorm;
    __shared__ unsigned s_task;

    const int tid  = threadIdx.x;
    const int wid  = tid >> 5;
    const int lane = tid & 31;

    uint32_t rank;
    asm("mov.u32 %0, %%cluster_ctarank;" : "=r"(rank));
    const int tensor = (int)(rank >> 1);     // 0 = sc, 1 = fc
    const int half   = (int)(rank & 1);      // rows [half*45, half*45+45)

    // ---- Once: stage pool_w, 1/||pool_w|| ----
    {
        float v = pool_w[tid];
        spw[tid] = v;
        float pw2 = v * v;
        #pragma unroll
        for (int off = 16; off; off >>= 1) pw2 += __shfl_xor_sync(0xffffffffu, pw2, off);
        if (lane == 0) red[wid] = pw2;
    }
    __syncthreads();
    if (tid == 0) {
        float s = 0.f;
        #pragma unroll
        for (int i = 0; i < WARPS; i++) s += red[i];
        s_invnorm = rsqrtf(s);
    }
    __syncthreads();

    const float inv_norm = s_invnorm;
    const float mw0 = multi_w[0];
    const float mw1 = multi_w[1];
    const float4* __restrict__ pw4 = (const float4*)spw;
    const uint32_t task_addr = smem_u32(&s_task);
    const uint32_t tanh_addr = smem_u32(&s_alltanh[0]);

    const float* __restrict__ X = (tensor == 0) ? x_sc : x_fc;
    float* __restrict__ OUT_T   = out + (size_t)tensor * BB * KK * DD;

    // Static per-warp task ids for the streaming phase (3-way interleave):
    // tasks t0 = wid, t1 = wid+32, t2 = wid+64 (t2 valid iff wid < 26).
    const int t0 = wid, t1 = wid + 32, t2 = wid + 64;
    const bool has2 = (t2 < 2 * ROWS_PER_CTA);          // warp-uniform
    const int base0 = (t0 >> 1) * 256 + (t0 & 1) * 128; // float4 idx of half-row
    const int base1 = (t1 >> 1) * 256 + (t1 & 1) * 128;
    const int base2 = has2 ? ((t2 >> 1) * 256 + (t2 & 1) * 128) : base0;
    const int pb0 = (t0 & 1) * 128;
    const int pb1 = (t1 & 1) * 128;
    const int pb2 = (t2 & 1) * 128;

    // ---- Persistent loop: one 4-CTA cluster = one batch ----
    for (;;) {
        if (rank == 0 && tid == 0) {
            unsigned t = atomicAdd(&g_task_counter, 1u);
            s_task = t;
            dsmem_st_u32(task_addr, 1u, t);
            dsmem_st_u32(task_addr, 2u, t);
            dsmem_st_u32(task_addr, 3u, t);
        }
        // SYNC A: publishes s_task; protects buf4/s_part reuse across iters.
        cluster_sync();
        const unsigned b = s_task;   // local smem read only (exit-safe)
        if (b >= BB) break;

        const float4* __restrict__ src4 =
            (const float4*)(X + (size_t)b * NN * DD + (size_t)half * ROWS_PER_CTA * DD);

        // ===== Stream tile: 3 half-rows per warp interleaved (MLP = 12) =====
        {
            float d0 = 0.f, d1 = 0.f, d2 = 0.f;
            #pragma unroll
            for (int m = 0; m < 4; m++) {
                const int j = lane + m * 32;          // 0..127
                float4 a0 = src4[base0 + j];
                float4 a1 = src4[base1 + j];
                float4 a2;
                if (has2) a2 = src4[base2 + j];
                buf4[base0 + j] = a0;
                buf4[base1 + j] = a1;
                if (has2) buf4[base2 + j] = a2;
                float4 p0 = pw4[pb0 + j];
                float4 p1 = pw4[pb1 + j];
                d0 += a0.x * p0.x + a0.y * p0.y + a0.z * p0.z + a0.w * p0.w;
                d1 += a1.x * p1.x + a1.y * p1.y + a1.z * p1.z + a1.w * p1.w;
                if (has2) {
                    float4 p2 = pw4[pb2 + j];
                    d2 += a2.x * p2.x + a2.y * p2.y + a2.z * p2.z + a2.w * p2.w;
                }
            }
            #pragma unroll
            for (int off = 16; off; off >>= 1) {
                d0 += __shfl_xor_sync(0xffffffffu, d0, off);
                d1 += __shfl_xor_sync(0xffffffffu, d1, off);
                d2 += __shfl_xor_sync(0xffffffffu, d2, off);
            }
            if (lane == 0) {
                s_part[t0] = d0;
                s_part[t1] = d1;
                if (has2) s_part[t2] = d2;
            }
        }
        __syncthreads();

        // ===== tanh for my 45 rows; publish to own + 3 peers =====
        if (tid < ROWS_PER_CTA) {
            float t0v = tanhf((s_part[2 * tid] + s_part[2 * tid + 1]) * inv_norm);
            const int node = half * ROWS_PER_CTA + tid;
            const uint32_t off = (uint32_t)(tensor * NN + node) * 4u;
            s_alltanh[tensor * NN + node] = t0v;
            #pragma unroll
            for (uint32_t p = 0; p < CLUSTER; p++)
                if (p != rank) dsmem_st_f32(tanh_addr + off, p, t0v);
        }
        // SYNC B: all 180 tanh values visible everywhere.
        cluster_sync();

        // ===== Scores + top-45 selection (redundant per CTA, cheap) =====
        if (tid < NN) {
            float z = s_alltanh[tid] * mw0 + s_alltanh[NN + tid] * mw1 + multi_b[tid];
            s_scores[tid] = 1.f / (1.f + expf(-z));
        }
        __syncthreads();
        if (tid < NN) {
            float my = s_scores[tid];
            int r = 0;
            #pragma unroll 10
            for (int j = 0; j < NN; j++) {
                float sj = s_scores[j];
                r += (sj > my) || (sj == my && j < tid);
            }
            if (r < KK) { sel_idx[r] = tid; sel_w[r] = my; }
        }
        __syncthreads();

        // ===== Write selected rows I own, straight from smem =====
        float* __restrict__ ob = OUT_T + (size_t)b * KK * DD;
        for (int k = wid; k < KK; k += WARPS) {
            const int n = sel_idx[k];
            const int local = n - half * ROWS_PER_CTA;
            if ((unsigned)local < (unsigned)ROWS_PER_CTA) {
                const float w = sel_w[k];
                const float4* srow = buf4 + (size_t)local * 256;
                float4* dst = (float4*)(ob + (size_t)k * DD);
                #pragma unroll
                for (int m = 0; m < 8; m++) {
                    const int j = lane + m * 32;
                    float4 v = srow[j];
                    v.x *= w; v.y *= w; v.z *= w; v.w *= w;
                    dst[j] = v;
                }
            }
        }
        // loop back: SYNC A protects buf4 before next iteration's STS
    }

    // Exit barrier: no CTA leaves while a peer might still push to its smem.
    cluster_sync();

    // ---- Last CTA resets device state for the next graph replay ----
    if (tid == 0) {
        unsigned d = atomicAdd(&g_done, 1u) + 1u;
        if (d == gridDim.x) {
            g_task_counter = 0;
            g_done = 0;
        }
    }
}

extern "C" void kernel_launch(void* const* d_in, const int* in_sizes, int n_in,
                              void* d_out, int out_size)
{
    const float* x_sc    = (const float*)d_in[0];
    const float* x_fc    = (const float*)d_in[1];
    const float* pool_w  = (const float*)d_in[2];
    const float* multi_w = (const float*)d_in[3];
    const float* multi_b = (const float*)d_in[4];
    float* out = (float*)d_out;

    static int inited = 0;
    if (!inited) {
        cudaFuncSetAttribute(multig_pool_kernel,
                             cudaFuncAttributeMaxDynamicSharedMemorySize, BUF_BYTES);
        inited = 1;
    }

    // 33 clusters x 4 CTAs = 132 CTAs (cluster-4 residency cap on 148 SMs).
    multig_pool_kernel<<<132, THREADS, BUF_BYTES>>>(x_sc, x_fc, pool_w, multi_w, multi_b, out);
}

// round 10
// speedup vs baseline: 1.1036x; 1.1036x over previous
#include <cuda_runtime.h>

#define BB 512
#define NN 90
#define DD 1024
#define KK 45
#define THREADS 512
#define WARPS 16
#define NSTASH 12                              // nodes stashed (x2 tensors)
#define STASH_BYTES (2 * NSTASH * DD * 4)      // 98304 B dynamic smem

__device__ unsigned g_task_counter;
__device__ unsigned g_done;

__global__ __launch_bounds__(THREADS, 2)
void multig_pool_kernel(const float* __restrict__ x_sc,
                        const float* __restrict__ x_fc,
                        const float* __restrict__ pool_w,
                        const float* __restrict__ multi_w,
                        const float* __restrict__ multi_b,
                        float* __restrict__ out)
{
    extern __shared__ __align__(16) float4 stash[];  // [2*NSTASH rows][256 f4]
    __shared__ __align__(16) float spw[DD];
    __shared__ float scores[NN];
    __shared__ int   sel_idx[KK];
    __shared__ float sel_w[KK];
    __shared__ float red[WARPS];
    __shared__ float s_invnorm;
    __shared__ unsigned s_task;

    const int tid  = threadIdx.x;
    const int wid  = tid >> 5;
    const int lane = tid & 31;

    // ---- Once per CTA: stage pool_w, compute 1/||pool_w|| ----
    float pw2 = 0.f;
    {
        float v0 = pool_w[tid];
        float v1 = pool_w[tid + THREADS];
        spw[tid]           = v0;
        spw[tid + THREADS] = v1;
        pw2 = v0 * v0 + v1 * v1;
    }
    #pragma unroll
    for (int off = 16; off; off >>= 1) pw2 += __shfl_xor_sync(0xffffffffu, pw2, off);
    if (lane == 0) red[wid] = pw2;
    __syncthreads();
    if (tid == 0) {
        float s = 0.f;
        #pragma unroll
        for (int i = 0; i < WARPS; i++) s += red[i];
        s_invnorm = rsqrtf(s);
    }
    __syncthreads();

    const float inv_norm = s_invnorm;
    const float mw0 = multi_w[0];
    const float mw1 = multi_w[1];
    const float4* __restrict__ pw4 = (const float4*)spw;

    // ---- Persistent loop: one task = one whole batch (R1 semantics) ----
    for (;;) {
        if (tid == 0) s_task = atomicAdd(&g_task_counter, 1u);
        __syncthreads();
        const unsigned b = s_task;
        if (b >= BB) break;

        const float* __restrict__ xb_sc = x_sc + (size_t)b * NN * DD;
        const float* __restrict__ xb_fc = x_fc + (size_t)b * NN * DD;

        // ===== Phase 1: dual dot-products, warp per node (MLP 16).
        // Nodes 0..NSTASH-1: also stash both rows in smem (free — data is
        // already in registers). These are the earliest-read rows, i.e. the
        // ones most likely evicted from L2 by gather time. =====
        for (int n = wid; n < NN; n += WARPS) {
            const float4* rs = (const float4*)(xb_sc + (size_t)n * DD);
            const float4* rf = (const float4*)(xb_fc + (size_t)n * DD);
            const bool do_stash = (n < NSTASH);           // warp-uniform
            float4* st_s = stash + (size_t)n * 256;
            float4* st_f = stash + (size_t)(NSTASH + n) * 256;
            float dsc = 0.f, dfc = 0.f;
            #pragma unroll
            for (int i = 0; i < 8; i++) {
                int j = lane + i * 32;
                float4 a = rs[j];
                float4 c = rf[j];
                float4 p = pw4[j];
                if (do_stash) { st_s[j] = a; st_f[j] = c; }
                dsc += a.x * p.x + a.y * p.y + a.z * p.z + a.w * p.w;
                dfc += c.x * p.x + c.y * p.y + c.z * p.z + c.w * p.w;
            }
            #pragma unroll
            for (int off = 16; off; off >>= 1) {
                dsc += __shfl_xor_sync(0xffffffffu, dsc, off);
                dfc += __shfl_xor_sync(0xffffffffu, dfc, off);
            }
            if (lane == 0) {
                float t0 = tanhf(dsc * inv_norm);
                float t1 = tanhf(dfc * inv_norm);
                float z  = t0 * mw0 + t1 * mw1 + multi_b[n];
                scores[n] = 1.f / (1.f + expf(-z));
            }
        }
        __syncthreads();

        // ===== Phase 2: rank-count selection (stable descending argsort) =====
        if (tid < NN) {
            float my = scores[tid];
            int rank = 0;
            #pragma unroll 10
            for (int j = 0; j < NN; j++) {
                float sj = scores[j];
                rank += (sj > my) || (sj == my && j < tid);
            }
            if (rank < KK) { sel_idx[rank] = tid; sel_w[rank] = my; }
        }
        __syncthreads();

        // ===== Phase 3: gather+scale, warp per output row.
        // n < NSTASH -> smem (guaranteed); else global (recent -> L2). =====
        float* __restrict__ out_sc = out + (size_t)b * KK * DD;
        float* __restrict__ out_fc = out + (size_t)BB * KK * DD + (size_t)b * KK * DD;

        for (int r = wid; r < 2 * KK; r += WARPS) {
            const bool is_sc = (r < KK);
            const int  k = is_sc ? r : r - KK;
            const int  n = sel_idx[k];
            const float w = sel_w[k];
            float4* dst = (float4*)((is_sc ? out_sc : out_fc) + (size_t)k * DD);
            if (n < NSTASH) {                               // warp-uniform
                const float4* src = stash + (size_t)((is_sc ? 0 : NSTASH) + n) * 256;
                #pragma unroll
                for (int i = 0; i < 8; i++) {
                    int j = lane + i * 32;
                    float4 v = src[j];
                    v.x *= w; v.y *= w; v.z *= w; v.w *= w;
                    dst[j] = v;
                }
            } else {
                const float4* src = (const float4*)((is_sc ? xb_sc : xb_fc) + (size_t)n * DD);
                #pragma unroll
                for (int i = 0; i < 8; i++) {
                    int j = lane + i * 32;
                    float4 v = src[j];
                    v.x *= w; v.y *= w; v.z *= w; v.w *= w;
                    dst[j] = v;
                }
            }
        }
        __syncthreads();   // protect stash/scores/sel before next iteration
    }

    // ---- Last CTA out resets queue state for the next graph replay ----
    if (tid == 0) {
        unsigned d = atomicAdd(&g_done, 1u) + 1u;
        if (d == gridDim.x) {
            g_task_counter = 0;
            g_done = 0;
        }
    }
}

extern "C" void kernel_launch(void* const* d_in, const int* in_sizes, int n_in,
                              void* d_out, int out_size)
{
    const float* x_sc    = (const float*)d_in[0];
    const float* x_fc    = (const float*)d_in[1];
    const float* pool_w  = (const float*)d_in[2];
    const float* multi_w = (const float*)d_in[3];
    const float* multi_b = (const float*)d_in[4];
    float* out = (float*)d_out;

    static int grid = 0;
    if (grid == 0) {
        int sm = 0;
        cudaDeviceGetAttribute(&sm, cudaDevAttrMultiProcessorCount, 0);
        if (sm <= 0) sm = 148;
        grid = 2 * sm;
        cudaFuncSetAttribute(multig_pool_kernel,
                             cudaFuncAttributeMaxDynamicSharedMemorySize, STASH_BYTES);
    }

    multig_pool_kernel<<<grid, THREADS, STASH_BYTES>>>(x_sc, x_fc, pool_w,
                                                       multi_w, multi_b, out);
}

// round 11
// speedup vs baseline: 1.2802x; 1.1600x over previous
#include <cuda_runtime.h>

#define BB 512
#define NN 90
#define DD 1024
#define KK 45
#define THREADS 512
#define WARPS 16
#define LAG 64                               // gather lags score by LAG batches
#define QTOT (BB + LAG)                      // q range
#define TOTAL_TASKS (6 * QTOT)

// Device-global scratch (no allocation allowed)
__device__ unsigned g_task_counter;
__device__ unsigned g_done;
__device__ unsigned g_arrive[BB];
__device__ float    g_scores[BB][NN];

__global__ __launch_bounds__(THREADS, 2)
void multig_pool_kernel(const float* __restrict__ x_sc,
                        const float* __restrict__ x_fc,
                        const float* __restrict__ pool_w,
                        const float* __restrict__ multi_w,
                        const float* __restrict__ multi_b,
                        float* __restrict__ out)
{
    __shared__ __align__(16) float spw[DD];
    __shared__ float s_scores[NN];
    __shared__ int   sel_idx[KK];
    __shared__ float sel_w[KK];
    __shared__ float red[WARPS];
    __shared__ float s_invnorm;
    __shared__ unsigned s_task;

    const int tid  = threadIdx.x;
    const int wid  = tid >> 5;
    const int lane = tid & 31;

    // ---- Once per CTA: stage pool_w, compute 1/||pool_w|| ----
    float pw2 = 0.f;
    {
        float v0 = pool_w[tid];
        float v1 = pool_w[tid + THREADS];
        spw[tid]           = v0;
        spw[tid + THREADS] = v1;
        pw2 = v0 * v0 + v1 * v1;
    }
    #pragma unroll
    for (int off = 16; off; off >>= 1) pw2 += __shfl_xor_sync(0xffffffffu, pw2, off);
    if (lane == 0) red[wid] = pw2;
    __syncthreads();
    if (tid == 0) {
        float s = 0.f;
        #pragma unroll
        for (int i = 0; i < WARPS; i++) s += red[i];
        s_invnorm = rsqrtf(s);
    }
    __syncthreads();

    const float inv_norm = s_invnorm;
    const float mw0 = multi_w[0];
    const float mw1 = multi_w[1];
    const float4* __restrict__ pw4 = (const float4*)spw;

    // ---- Persistent interleaved task stream ----
    // t = 6q + r.  r<4: score quarter r of batch q.  r>=4: gather half (r-4)
    // of batch q-LAG.  Lag (6*LAG+1 = 385 slots) > concurrency (304 CTAs), so
    // gathers practically never spin, and scorers NEVER wait.
    for (;;) {
        if (tid == 0) s_task = atomicAdd(&g_task_counter, 1u);
        __syncthreads();
        const unsigned t = s_task;
        if (t >= TOTAL_TASKS) break;

        const unsigned q = t / 6u;
        const unsigned r = t % 6u;

        if (r < 4u) {
            // ============ SCORE QUARTER: batch q, quarter r ============
            if (q < BB) {
                const int b  = (int)q;
                const int qt = (int)r;
                const float* __restrict__ xb_sc = x_sc + (size_t)b * NN * DD;
                const float* __restrict__ xb_fc = x_fc + (size_t)b * NN * DD;

                const int cnt = (NN - qt + 3) >> 2;   // 23,23,22,22
                for (int j = wid; j < cnt; j += WARPS) {
                    const int n = qt + 4 * j;
                    const float4* rs = (const float4*)(xb_sc + (size_t)n * DD);
                    const float4* rf = (const float4*)(xb_fc + (size_t)n * DD);
                    float dsc = 0.f, dfc = 0.f;
                    #pragma unroll
                    for (int i = 0; i < 8; i++) {
                        int jj = lane + i * 32;
                        float4 a = rs[jj];
                        float4 c = rf[jj];
                        float4 p = pw4[jj];
                        dsc += a.x * p.x + a.y * p.y + a.z * p.z + a.w * p.w;
                        dfc += c.x * p.x + c.y * p.y + c.z * p.z + c.w * p.w;
                    }
                    #pragma unroll
                    for (int off = 16; off; off >>= 1) {
                        dsc += __shfl_xor_sync(0xffffffffu, dsc, off);
                        dfc += __shfl_xor_sync(0xffffffffu, dfc, off);
                    }
                    if (lane == 0) {
                        float t0 = tanhf(dsc * inv_norm);
                        float t1 = tanhf(dfc * inv_norm);
                        float z  = t0 * mw0 + t1 * mw1 + multi_b[n];
                        g_scores[b][n] = 1.f / (1.f + expf(-z));
                    }
                }
                __syncthreads();
                if (tid == 0) {
                    __threadfence();
                    atomicAdd(&g_arrive[b], 1u);
                }
            }
        } else {
            // ============ GATHER: batch q-LAG, tensor half r-4 ============
            if (q >= LAG && q - LAG < BB) {
                const int b    = (int)(q - LAG);
                const int half = (int)(r - 4u);   // 0 = sc, 1 = fc

                if (tid == 0) {
                    while (atomicAdd(&g_arrive[b], 0u) < 4u) { }
                }
                __syncthreads();
                __threadfence();

                // Scores -> smem, redundant top-45 selection (cheap)
                if (tid < NN) s_scores[tid] = g_scores[b][tid];
                __syncthreads();
                if (tid < NN) {
                    float my = s_scores[tid];
                    int rk = 0;
                    #pragma unroll 10
                    for (int j = 0; j < NN; j++) {
                        float sj = s_scores[j];
                        rk += (sj > my) || (sj == my && j < tid);
                    }
                    if (rk < KK) { sel_idx[rk] = tid; sel_w[rk] = my; }
                }
                __syncthreads();

                const float* __restrict__ xb =
                    (half == 0 ? x_sc : x_fc) + (size_t)b * NN * DD;
                float* __restrict__ ob = out
                    + (size_t)half * BB * KK * DD + (size_t)b * KK * DD;

                for (int k = wid; k < KK; k += WARPS) {
                    const int   n = sel_idx[k];
                    const float w = sel_w[k];
                    const float4* src = (const float4*)(xb + (size_t)n * DD);
                    float4* dst = (float4*)(ob + (size_t)k * DD);
                    #pragma unroll
                    for (int i = 0; i < 8; i++) {
                        int j = lane + i * 32;
                        float4 v = src[j];
                        v.x *= w; v.y *= w; v.z *= w; v.w *= w;
                        dst[j] = v;
                    }
                }
            }
        }
        __syncthreads();   // protect s_task / s_scores / sel reuse
    }

    // ---- Last CTA out resets device state for next graph replay ----
    if (tid == 0) atomicAdd(&g_done, 1u);
    if (tid == 0) {
        // Only the last CTA performs the reset.
        if (atomicAdd(&g_done, 0u) == gridDim.x) {
            // This CTA observed itself as last; reset everything.
            g_task_counter = 0;
        }
    }
    __syncthreads();
    // Re-check with all threads so the arrive array reset is parallel:
    __shared__ unsigned s_is_last;
    if (tid == 0) s_is_last = (atomicAdd(&g_done, 0u) == gridDim.x) ? 1u : 0u;
    __syncthreads();
    if (s_is_last) {
        for (int i = tid; i < BB; i += THREADS) g_arrive[i] = 0;
        __syncthreads();
        if (tid == 0) { __threadfence(); g_done = 0; }
    }
}

extern "C" void kernel_launch(void* const* d_in, const int* in_sizes, int n_in,
                              void* d_out, int out_size)
{
    const float* x_sc    = (const float*)d_in[0];
    const float* x_fc    = (const float*)d_in[1];
    const float* pool_w  = (const float*)d_in[2];
    const float* multi_w = (const float*)d_in[3];
    const float* multi_b = (const float*)d_in[4];
    float* out = (float*)d_out;

    static int grid = 0;
    if (grid == 0) {
        int sm = 0;
        cudaDeviceGetAttribute(&sm, cudaDevAttrMultiProcessorCount, 0);
        if (sm <= 0) sm = 148;
        grid = 2 * sm;
    }

    multig_pool_kernel<<<grid, THREADS>>>(x_sc, x_fc, pool_w, multi_w, multi_b, out);
}

// round 12
// speedup vs baseline: 1.3185x; 1.0300x over previous
#include <cuda_runtime.h>

#define BB 512
#define NN 90
#define DD 1024
#define KK 45
#define THREADS 256
#define WARPS 8
#define LAG 100                              // gather lags score by LAG batches
#define QTOT (BB + LAG)
#define TOTAL_TASKS (6 * QTOT)

// Device-global scratch (no allocation allowed)
__device__ unsigned g_task_counter;
__device__ unsigned g_done;
__device__ unsigned g_arrive[BB];
__device__ float    g_scores[BB][NN];

__global__ __launch_bounds__(THREADS, 4)
void multig_pool_kernel(const float* __restrict__ x_sc,
                        const float* __restrict__ x_fc,
                        const float* __restrict__ pool_w,
                        const float* __restrict__ multi_w,
                        const float* __restrict__ multi_b,
                        float* __restrict__ out)
{
    __shared__ __align__(16) float spw[DD];
    __shared__ float s_scores[NN];
    __shared__ int   sel_idx[KK];
    __shared__ float sel_w[KK];
    __shared__ float red[WARPS];
    __shared__ float s_invnorm;
    __shared__ unsigned s_task;

    const int tid  = threadIdx.x;
    const int wid  = tid >> 5;
    const int lane = tid & 31;

    // ---- Once per CTA: stage pool_w, compute 1/||pool_w|| ----
    float pw2 = 0.f;
    #pragma unroll
    for (int i = 0; i < 4; i++) {
        float v = pool_w[tid + i * THREADS];
        spw[tid + i * THREADS] = v;
        pw2 += v * v;
    }
    #pragma unroll
    for (int off = 16; off; off >>= 1) pw2 += __shfl_xor_sync(0xffffffffu, pw2, off);
    if (lane == 0) red[wid] = pw2;
    __syncthreads();
    if (tid == 0) {
        float s = 0.f;
        #pragma unroll
        for (int i = 0; i < WARPS; i++) s += red[i];
        s_invnorm = rsqrtf(s);
    }
    __syncthreads();

    const float inv_norm = s_invnorm;
    const float mw0 = multi_w[0];
    const float mw1 = multi_w[1];
    const float4* __restrict__ pw4 = (const float4*)spw;

    // ---- Persistent interleaved task stream ----
    // t = 6q + r.  r<4: score quarter r of batch q.  r>=4: gather half (r-4)
    // of batch q-LAG.  Dequeue distance (6*LAG+1 = 601) >= concurrency (592),
    // so gathers essentially never spin; scorers NEVER wait.
    for (;;) {
        // NOTE: loop-top sync is the ONLY inter-task barrier needed: a warp
        // reaches it only after finishing its previous task, so overwriting
        // s_task / s_scores / sel_* after it is safe.
        if (tid == 0) s_task = atomicAdd(&g_task_counter, 1u);
        __syncthreads();
        const unsigned t = s_task;
        if (t >= TOTAL_TASKS) break;

        const unsigned q = t / 6u;
        const unsigned r = t % 6u;

        if (r < 4u) {
            // ============ SCORE QUARTER: batch q, quarter r ============
            if (q < BB) {
                const int b  = (int)q;
                const int qt = (int)r;
                const float* __restrict__ xb_sc = x_sc + (size_t)b * NN * DD;
                const float* __restrict__ xb_fc = x_fc + (size_t)b * NN * DD;

                const int cnt = (NN - qt + 3) >> 2;   // 23,23,22,22
                for (int j = wid; j < cnt; j += WARPS) {
                    const int n = qt + 4 * j;
                    const float4* rs = (const float4*)(xb_sc + (size_t)n * DD);
                    const float4* rf = (const float4*)(xb_fc + (size_t)n * DD);
                    float dsc = 0.f, dfc = 0.f;
                    #pragma unroll
                    for (int i = 0; i < 8; i++) {
                        int jj = lane + i * 32;
                        float4 a = rs[jj];
                        float4 c = rf[jj];
                        float4 p = pw4[jj];
                        dsc += a.x * p.x + a.y * p.y + a.z * p.z + a.w * p.w;
                        dfc += c.x * p.x + c.y * p.y + c.z * p.z + c.w * p.w;
                    }
                    #pragma unroll
                    for (int off = 16; off; off >>= 1) {
                        dsc += __shfl_xor_sync(0xffffffffu, dsc, off);
                        dfc += __shfl_xor_sync(0xffffffffu, dfc, off);
                    }
                    if (lane == 0) {
                        float t0 = tanhf(dsc * inv_norm);
                        float t1 = tanhf(dfc * inv_norm);
                        float z  = t0 * mw0 + t1 * mw1 + multi_b[n];
                        g_scores[b][n] = 1.f / (1.f + expf(-z));
                    }
                }
                __syncthreads();                 // all g_scores writes done
                if (tid == 0) {
                    __threadfence();
                    atomicAdd(&g_arrive[b], 1u);
                }
            }
        } else {
            // ============ GATHER: batch q-LAG, tensor half r-4 ============
            if (q >= LAG && q - LAG < BB) {
                const int b    = (int)(q - LAG);
                const int half = (int)(r - 4u);   // 0 = sc, 1 = fc

                if (tid == 0) {
                    while (atomicAdd(&g_arrive[b], 0u) < 4u) { }
                }
                __syncthreads();

                // Scores -> smem (L2-coherent loads), redundant selection
                if (tid < NN) s_scores[tid] = __ldcg(&g_scores[b][tid]);
                __syncthreads();
                if (tid < NN) {
                    float my = s_scores[tid];
                    int rk = 0;
                    #pragma unroll 10
                    for (int j = 0; j < NN; j++) {
                        float sj = s_scores[j];
                        rk += (sj > my) || (sj == my && j < tid);
                    }
                    if (rk < KK) { sel_idx[rk] = tid; sel_w[rk] = my; }
                }
                __syncthreads();

                const float* __restrict__ xb =
                    (half == 0 ? x_sc : x_fc) + (size_t)b * NN * DD;
                float* __restrict__ ob = out
                    + (size_t)half * BB * KK * DD + (size_t)b * KK * DD;

                for (int k = wid; k < KK; k += WARPS) {
                    const int   n = sel_idx[k];
                    const float w = sel_w[k];
                    const float4* src = (const float4*)(xb + (size_t)n * DD);
                    float4* dst = (float4*)(ob + (size_t)k * DD);
                    #pragma unroll
                    for (int i = 0; i < 8; i++) {
                        int j = lane + i * 32;
                        float4 v = src[j];
                        v.x *= w; v.y *= w; v.z *= w; v.w *= w;
                        dst[j] = v;
                    }
                }
            }
        }
        // no trailing sync — loop-top sync covers reuse hazards
    }

    // ---- Last CTA out resets device state for the next graph replay ----
    __shared__ unsigned s_is_last;
    if (tid == 0) {
        unsigned d = atomicAdd(&g_done, 1u) + 1u;
        s_is_last = (d == gridDim.x) ? 1u : 0u;
    }
    __syncthreads();
    if (s_is_last) {
        for (int i = tid; i < BB; i += THREADS) g_arrive[i] = 0;
        __syncthreads();
        if (tid == 0) {
            g_task_counter = 0;
            __threadfence();
            g_done = 0;
        }
    }
}

extern "C" void kernel_launch(void* const* d_in, const int* in_sizes, int n_in,
                              void* d_out, int out_size)
{
    const float* x_sc    = (const float*)d_in[0];
    const float* x_fc    = (const float*)d_in[1];
    const float* pool_w  = (const float*)d_in[2];
    const float* multi_w = (const float*)d_in[3];
    const float* multi_b = (const float*)d_in[4];
    float* out = (float*)d_out;

    static int grid = 0;
    if (grid == 0) {
        int sm = 0;
        cudaDeviceGetAttribute(&sm, cudaDevAttrMultiProcessorCount, 0);
        if (sm <= 0) sm = 148;
        grid = 4 * sm;   // 4 CTAs/SM x 256 thr: regs 4*256*64 = 64K exactly
    }

    multig_pool_kernel<<<grid, THREADS>>>(x_sc, x_fc, pool_w, multi_w, multi_b, out);
}

// round 13
// speedup vs baseline: 1.3508x; 1.0245x over previous
#include <cuda_runtime.h>

#define BB 512
#define NN 90
#define DD 1024
#define KK 45
#define THREADS 256
#define WARPS 8
#define LAG 50                               // gather lags score by LAG batches
#define QTOT (BB + LAG)
#define TOTAL_TASKS (12 * QTOT)

// Device-global scratch (no allocation allowed)
__device__ unsigned g_task_counter;
__device__ unsigned g_done;
__device__ unsigned g_arrive[BB];
__device__ float    g_scores[BB][NN];

__global__ __launch_bounds__(THREADS, 4)
void multig_pool_kernel(const float* __restrict__ x_sc,
                        const float* __restrict__ x_fc,
                        const float* __restrict__ pool_w,
                        const float* __restrict__ multi_w,
                        const float* __restrict__ multi_b,
                        float* __restrict__ out)
{
    __shared__ __align__(16) float spw[DD];
    __shared__ float s_scores[NN];
    __shared__ int   sel_idx[KK];
    __shared__ float sel_w[KK];
    __shared__ float red[WARPS];
    __shared__ float s_invnorm;
    __shared__ unsigned s_task;

    const int tid  = threadIdx.x;
    const int wid  = tid >> 5;
    const int lane = tid & 31;

    // ---- Once per CTA: stage pool_w, compute 1/||pool_w|| ----
    float pw2 = 0.f;
    #pragma unroll
    for (int i = 0; i < 4; i++) {
        float v = pool_w[tid + i * THREADS];
        spw[tid + i * THREADS] = v;
        pw2 += v * v;
    }
    #pragma unroll
    for (int off = 16; off; off >>= 1) pw2 += __shfl_xor_sync(0xffffffffu, pw2, off);
    if (lane == 0) red[wid] = pw2;
    __syncthreads();
    if (tid == 0) {
        float s = 0.f;
        #pragma unroll
        for (int i = 0; i < WARPS; i++) s += red[i];
        s_invnorm = rsqrtf(s);
    }
    __syncthreads();

    const float inv_norm = s_invnorm;
    const float mw0 = multi_w[0];
    const float mw1 = multi_w[1];
    const float4* __restrict__ pw4 = (const float4*)spw;

    // ---- Persistent interleaved task stream, 12 tasks per batch ----
    // t = 12q + r.  r<8: score eighth r of batch q (nodes r, r+8, ...).
    // r>=8: gather quarter (r-8) of batch q-LAG (output rows (r-8)+4m, both
    // tensors). Dequeue distance 12*LAG = 600 >= concurrency 592 (no spins);
    // score->gather time gap ~= 600 slots / ~62 tasks/us ~= 10us < L2 life.
    for (;;) {
        // Loop-top sync is the only inter-task barrier needed: a warp reaches
        // it only after finishing its prior task.
        if (tid == 0) s_task = atomicAdd(&g_task_counter, 1u);
        __syncthreads();
        const unsigned t = s_task;
        if (t >= TOTAL_TASKS) break;

        const unsigned q = t / 12u;
        const unsigned r = t % 12u;

        if (r < 8u) {
            // ============ SCORE EIGHTH: batch q, nodes r + 8j ============
            if (q < BB) {
                const int b = (int)q;
                const int e = (int)r;
                const float* __restrict__ xb_sc = x_sc + (size_t)b * NN * DD;
                const float* __restrict__ xb_fc = x_fc + (size_t)b * NN * DD;

                const int cnt = (NN - e + 7) >> 3;    // 12 or 11
                for (int j = wid; j < cnt; j += WARPS) {
                    const int n = e + 8 * j;
                    const float4* rs = (const float4*)(xb_sc + (size_t)n * DD);
                    const float4* rf = (const float4*)(xb_fc + (size_t)n * DD);
                    float dsc = 0.f, dfc = 0.f;
                    #pragma unroll
                    for (int i = 0; i < 8; i++) {
                        int jj = lane + i * 32;
                        float4 a = rs[jj];
                        float4 c = rf[jj];
                        float4 p = pw4[jj];
                        dsc += a.x * p.x + a.y * p.y + a.z * p.z + a.w * p.w;
                        dfc += c.x * p.x + c.y * p.y + c.z * p.z + c.w * p.w;
                    }
                    #pragma unroll
                    for (int off = 16; off; off >>= 1) {
                        dsc += __shfl_xor_sync(0xffffffffu, dsc, off);
                        dfc += __shfl_xor_sync(0xffffffffu, dfc, off);
                    }
                    if (lane == 0) {
                        float t0 = tanhf(dsc * inv_norm);
                        float t1 = tanhf(dfc * inv_norm);
                        float z  = t0 * mw0 + t1 * mw1 + multi_b[n];
                        g_scores[b][n] = 1.f / (1.f + expf(-z));
                    }
                }
                __syncthreads();                 // all g_scores writes done
                if (tid == 0) {
                    __threadfence();
                    atomicAdd(&g_arrive[b], 1u);
                }
            }
        } else {
            // ======= GATHER QUARTER: batch q-LAG, rows (r-8)+4m =======
            if (q >= LAG && q - LAG < BB) {
                const int b  = (int)(q - LAG);
                const int qt = (int)(r - 8u);

                if (tid == 0) {
                    while (atomicAdd(&g_arrive[b], 0u) < 8u) { }
                }
                __syncthreads();

                // Scores -> smem, redundant top-45 selection (cheap)
                if (tid < NN) s_scores[tid] = __ldcg(&g_scores[b][tid]);
                __syncthreads();
                if (tid < NN) {
                    float my = s_scores[tid];
                    int rk = 0;
                    #pragma unroll 10
                    for (int j = 0; j < NN; j++) {
                        float sj = s_scores[j];
                        rk += (sj > my) || (sj == my && j < tid);
                    }
                    if (rk < KK) { sel_idx[rk] = tid; sel_w[rk] = my; }
                }
                __syncthreads();

                const float* __restrict__ xb_sc = x_sc + (size_t)b * NN * DD;
                const float* __restrict__ xb_fc = x_fc + (size_t)b * NN * DD;
                float* __restrict__ out_sc = out + (size_t)b * KK * DD;
                float* __restrict__ out_fc = out + (size_t)BB * KK * DD
                                                 + (size_t)b * KK * DD;

                // Output rows qt, qt+4, ... over both tensors (2*KK = 90)
                const int cnt2 = (2 * KK - qt + 3) >> 2;   // 23 or 22
                for (int m = wid; m < cnt2; m += WARPS) {
                    const int rr = qt + 4 * m;
                    const bool is_sc = (rr < KK);
                    const int  k = is_sc ? rr : rr - KK;
                    const int  n = sel_idx[k];
                    const float w = sel_w[k];
                    const float4* src = (const float4*)
                        ((is_sc ? xb_sc : xb_fc) + (size_t)n * DD);
                    float4* dst = (float4*)
                        ((is_sc ? out_sc : out_fc) + (size_t)k * DD);
                    #pragma unroll
                    for (int i = 0; i < 8; i++) {
                        int j = lane + i * 32;
                        float4 v = src[j];
                        v.x *= w; v.y *= w; v.z *= w; v.w *= w;
                        dst[j] = v;
                    }
                }
            }
        }
        // no trailing sync — loop-top sync covers reuse hazards
    }

    // ---- Last CTA out resets device state for the next graph replay ----
    __shared__ unsigned s_is_last;
    if (tid == 0) {
        unsigned d = atomicAdd(&g_done, 1u) + 1u;
        s_is_last = (d == gridDim.x) ? 1u : 0u;
    }
    __syncthreads();
    if (s_is_last) {
        for (int i = tid; i < BB; i += THREADS) g_arrive[i] = 0;
        __syncthreads();
        if (tid == 0) {
            g_task_counter = 0;
            __threadfence();
            g_done = 0;
        }
    }
}

extern "C" void kernel_launch(void* const* d_in, const int* in_sizes, int n_in,
                              void* d_out, int out_size)
{
    const float* x_sc    = (const float*)d_in[0];
    const float* x_fc    = (const float*)d_in[1];
    const float* pool_w  = (const float*)d_in[2];
    const float* multi_w = (const float*)d_in[3];
    const float* multi_b = (const float*)d_in[4];
    float* out = (float*)d_out;

    static int grid = 0;
    if (grid == 0) {
        int sm = 0;
        cudaDeviceGetAttribute(&sm, cudaDevAttrMultiProcessorCount, 0);
        if (sm <= 0) sm = 148;
        grid = 4 * sm;   // 4 CTAs/SM x 256 thr
    }

    multig_pool_kernel<<<grid, THREADS>>>(x_sc, x_fc, pool_w, multi_w, multi_b, out);
}